// round 5
// baseline (speedup 1.0000x reference)
#include <cuda_runtime.h>
#include <math.h>

#define BB 2
#define NN 160
#define HH 256
#define C3 768
#define FF 512
#define NP (NN*NN)            // 25600
#define MM (BB*NN)            // 320
#define LOGIT_ELEMS (BB*NP*2) // 102400 per head
#define EMB_OFF (3*LOGIT_ELEMS)

// PQ scratch, split-K2: [h = (t*2+s)*2+ks][m][f]
__device__ float g_PQ[3 * 2 * 2 * MM * FF];
__device__ int g_done;

#define FFMA2(acc, a, b) asm("fma.rn.f32x2 %0, %1, %2, %0;" : "+l"(acc) : "l"(a), "l"(b))
#define PACKDUP(d, x)    asm("mov.b64 %0, {%1, %1};" : "=l"(d) : "r"(__float_as_uint(x)))
#define UNPK(lo, hi, v)  asm("mov.b64 {%0, %1}, %2;" : "=r"(lo), "=r"(hi) : "l"(v))

// ---------------- block-role layout ----------------
#define BM 64
#define BN 64
#define BK 16
#define NKS 24
#define AST 68
#define GEMM_BLOCKS 480
#define WRA_BLOCKS 2000
#define LG_BLOCKS 150
#define WRB_BLOCKS 1200
#define TOTAL_BLOCKS (GEMM_BLOCKS + WRA_BLOCKS + LG_BLOCKS + WRB_BLOCKS)

__global__ void k_reset() { g_done = 0; }

// writer: 16 pairs (same i) per 256-thread block, batched LDG (MLP=6)
__device__ __forceinline__ void writer_role(
    int wb,
    const float* __restrict__ geo, const float* __restrict__ app, const float* __restrict__ con,
    float* __restrict__ out, int tid)
{
    const int b = wb / 1600;
    const int rem = wb % 1600;
    const int i = rem / 10;
    const int j0 = (rem % 10) * 16;
    const size_t brow = (size_t)b * NN * HH;
    float4* dst0 = (float4*)(out + EMB_OFF) + (size_t)(b*NP + i*NN + j0) * 384;

    #pragma unroll
    for (int base = 0; base < 24; base += 6) {
        float4 vals[6];
        #pragma unroll
        for (int w = 0; w < 6; w++) {
            const int lin = tid + (base + w) * 256;   // 0..6143
            const int jj = lin / 384;
            const int u  = lin - jj * 384;
            const bool jside = (u < 192);
            const int n = jside ? (j0 + jj) : i;
            const int c = (jside ? u : (u - 192)) * 4;
            const float* bp = (c < 256) ? geo : ((c < 512) ? app : con);
            vals[w] = *(const float4*)(bp + brow + (size_t)n * HH + (c & 255));
        }
        #pragma unroll
        for (int w = 0; w < 6; w++)
            __stcs(dst0 + (base + w) * 256 + tid, vals[w]);
    }
}

__global__ __launch_bounds__(256) void k_main(
    const float* __restrict__ geo, const float* __restrict__ app, const float* __restrict__ con,
    const float* __restrict__ W1c, const float* __restrict__ b1c,
    const float* __restrict__ W1r, const float* __restrict__ b1r,
    const float* __restrict__ W1l, const float* __restrict__ b1l,
    const float* __restrict__ W2c, const float* __restrict__ b2c,
    const float* __restrict__ W2r, const float* __restrict__ b2r,
    const float* __restrict__ W2l, const float* __restrict__ b2l,
    float* __restrict__ out)
{
    __shared__ float smem[2*BK*AST + 2*BK*BN > 32*132 + 32*128 + 128 ?
                          2*BK*AST + 2*BK*BN : 32*132 + 32*128 + 128];
    const int g = blockIdx.x;
    const int tid = threadIdx.x;

    if (g < GEMM_BLOCKS) {
        // ================= GEMM role =================
        float (*As)[BK*AST] = (float(*)[BK*AST])smem;
        float (*Bs)[BK*BN]  = (float(*)[BK*BN])(smem + 2*BK*AST);
        const int nt = g % 48;
        const int r  = g / 48;
        const int mt = r >> 1;
        const int ks = r & 1;
        const int t  = nt >> 4;
        const int s  = (nt >> 3) & 1;
        const int f0 = (nt & 7) * BN;
        const float* W1 = (t==0 ? W1c : (t==1 ? W1r : W1l)) + (size_t)s * C3 * FF;
        const float* b1 = (t==0 ? b1c : (t==1 ? b1r : b1l));
        const int m0 = mt * BM;
        const int kbase = ks * 384;

        const int arow = tid >> 2, av = tid & 3;
        const int kr = tid >> 4, fo = (tid & 15) * 4;
        const int rg = tid >> 4, cg = tid & 15;

        unsigned long long acc2[4][2];
        #pragma unroll
        for (int a = 0; a < 4; a++) { acc2[a][0] = 0ull; acc2[a][1] = 0ull; }

        float4 pa, pb;
        {
            const int c0 = kbase;
            const float* segp = (c0 < 256) ? geo : ((c0 < 512) ? app : con);
            pa = *(const float4*)(segp + (size_t)(m0 + arow) * HH + (c0 & 255) + av * 4);
            pb = *(const float4*)(W1 + (size_t)(c0 + kr) * FF + f0 + fo);
        }
        As[0][(av*4+0)*AST + arow] = pa.x;
        As[0][(av*4+1)*AST + arow] = pa.y;
        As[0][(av*4+2)*AST + arow] = pa.z;
        As[0][(av*4+3)*AST + arow] = pa.w;
        *(float4*)&Bs[0][kr*BN + fo] = pb;
        __syncthreads();

        for (int kt = 0; kt < NKS; kt++) {
            const int cur = kt & 1;
            const int nxt = cur ^ 1;
            if (kt + 1 < NKS) {
                const int c0 = kbase + (kt + 1) * BK;
                const float* segp = (c0 < 256) ? geo : ((c0 < 512) ? app : con);
                pa = *(const float4*)(segp + (size_t)(m0 + arow) * HH + (c0 & 255) + av * 4);
                pb = *(const float4*)(W1 + (size_t)(c0 + kr) * FF + f0 + fo);
            }
            #pragma unroll
            for (int k = 0; k < BK; k++) {
                const float4 a4 = *(const float4*)&As[cur][k*AST + rg*4];
                const ulonglong2 b2v = *(const ulonglong2*)&Bs[cur][k*BN + cg*4];
                float avv[4] = {a4.x, a4.y, a4.z, a4.w};
                #pragma unroll
                for (int a = 0; a < 4; a++) {
                    unsigned long long ad;
                    PACKDUP(ad, avv[a]);
                    FFMA2(acc2[a][0], ad, b2v.x);
                    FFMA2(acc2[a][1], ad, b2v.y);
                }
            }
            if (kt + 1 < NKS) {
                __syncthreads();
                As[nxt][(av*4+0)*AST + arow] = pa.x;
                As[nxt][(av*4+1)*AST + arow] = pa.y;
                As[nxt][(av*4+2)*AST + arow] = pa.z;
                As[nxt][(av*4+3)*AST + arow] = pa.w;
                *(float4*)&Bs[nxt][kr*BN + fo] = pb;
                __syncthreads();
            }
        }

        const bool addb = (s == 1) && (ks == 0);
        float bv[4] = {0.f, 0.f, 0.f, 0.f};
        if (addb) {
            const float4 tb = *(const float4*)(b1 + f0 + cg*4);
            bv[0]=tb.x; bv[1]=tb.y; bv[2]=tb.z; bv[3]=tb.w;
        }
        const size_t hb = ((size_t)((t*2 + s) * 2 + ks)) * MM * FF;
        #pragma unroll
        for (int a = 0; a < 4; a++) {
            const int m = m0 + rg*4 + a;
            unsigned int lo0, hi0, lo1, hi1;
            UNPK(lo0, hi0, acc2[a][0]);
            UNPK(lo1, hi1, acc2[a][1]);
            *(float4*)(g_PQ + hb + (size_t)m * FF + f0 + cg*4) =
                make_float4(__uint_as_float(lo0) + bv[0], __uint_as_float(hi0) + bv[1],
                            __uint_as_float(lo1) + bv[2], __uint_as_float(hi1) + bv[3]);
        }
        // release-arrive
        __syncthreads();
        if (tid == 0) {
            __threadfence();
            atomicAdd(&g_done, 1);
        }
    } else if (g < GEMM_BLOCKS + WRA_BLOCKS) {
        writer_role(g - GEMM_BLOCKS, geo, app, con, out, tid);
    } else if (g < GEMM_BLOCKS + WRA_BLOCKS + LG_BLOCKS) {
        // ================= logits role (waits on GEMM) =================
        if (tid == 0) {
            int v;
            do {
                asm volatile("ld.acquire.gpu.u32 %0, [%1];" : "=r"(v) : "l"(&g_done) : "memory");
                if (v < GEMM_BLOCKS) __nanosleep(128);
            } while (v < GEMM_BLOCKS);
        }
        __syncthreads();

        float* sP = smem;              // 32*132
        float* sQ = smem + 32*132;     // 32*128
        float* sW = sQ + 32*128;       // 128
        const int lg = g - (GEMM_BLOCKS + WRA_BLOCKS);
        const int t = lg / 50;
        const int r50 = lg % 50;
        const int b = r50 / 25;
        const int r25 = r50 % 25;
        const int i0 = (r25 / 5) * 32;
        const int j0 = (r25 % 5) * 32;
        const float* W2 = (t==0 ? W2c : (t==1 ? W2r : W2l));
        const float* b2 = (t==0 ? b2c : (t==1 ? b2r : b2l));
        const size_t boff = (size_t)b * NN * FF;
        const float* P0 = g_PQ + ((size_t)((t*2+0)*2+0)) * MM * FF + boff;
        const float* P1 = g_PQ + ((size_t)((t*2+0)*2+1)) * MM * FF + boff;
        const float* Q0 = g_PQ + ((size_t)((t*2+1)*2+0)) * MM * FF + boff;
        const float* Q1 = g_PQ + ((size_t)((t*2+1)*2+1)) * MM * FF + boff;
        const int il = tid >> 5, jl = tid & 31;
        const int lr = tid >> 3, lv = tid & 7;

        float acc[4] = {0.f, 0.f, 0.f, 0.f};
        for (int fc = 0; fc < 4; fc++) {
            const int f0 = fc * 128;
            {
                const size_t ro = (size_t)(j0 + lr) * FF + f0;
                float* dp = sP + lr * 132;
                #pragma unroll
                for (int u = 0; u < 4; u++) {
                    const int fl = (lv + u * 8) * 4;
                    const float4 x = *(const float4*)(P0 + ro + fl);
                    const float4 y = *(const float4*)(P1 + ro + fl);
                    *(float4*)(dp + fl) = make_float4(x.x+y.x, x.y+y.y, x.z+y.z, x.w+y.w);
                }
            }
            {
                const size_t ro = (size_t)(i0 + lr) * FF + f0;
                float* dp = sQ + lr * 128;
                #pragma unroll
                for (int u = 0; u < 4; u++) {
                    const int fl = (lv + u * 8) * 4;
                    const float4 x = *(const float4*)(Q0 + ro + fl);
                    const float4 y = *(const float4*)(Q1 + ro + fl);
                    *(float4*)(dp + fl) = make_float4(x.x+y.x, x.y+y.y, x.z+y.z, x.w+y.w);
                }
            }
            if (tid < 128) {
                const float2 w2v = ((const float2*)W2)[f0 + tid];
                sW[tid] = w2v.x - w2v.y;
            }
            __syncthreads();

            const float* pr = sP + jl * 132;
            const float* q0 = sQ + (il * 4) * 128;
            #pragma unroll 4
            for (int f = 0; f < 128; f += 4) {
                const float4 p = *(const float4*)(pr + f);
                const float4 w = *(const float4*)(sW + f);
                #pragma unroll
                for (int a = 0; a < 4; a++) {
                    const float4 q = *(const float4*)(q0 + a * 128 + f);
                    acc[a] = fmaf(fmaxf(p.x + q.x, 0.f), w.x, acc[a]);
                    acc[a] = fmaf(fmaxf(p.y + q.y, 0.f), w.y, acc[a]);
                    acc[a] = fmaf(fmaxf(p.z + q.z, 0.f), w.z, acc[a]);
                    acc[a] = fmaf(fmaxf(p.w + q.w, 0.f), w.w, acc[a]);
                }
            }
            __syncthreads();
        }

        const float bd = b2[0] - b2[1];
        float2* o = (float2*)(out + (size_t)t * LOGIT_ELEMS) + (size_t)b * NP;
        const int j = j0 + jl;
        #pragma unroll
        for (int a = 0; a < 4; a++) {
            const float d = acc[a] + bd;
            const float p0 = 1.0f / (1.0f + __expf(-d));
            o[(size_t)(i0 + il*4 + a) * NN + j] = make_float2(p0, 1.0f - p0);
        }
    } else {
        writer_role(WRA_BLOCKS + (g - (GEMM_BLOCKS + WRA_BLOCKS + LG_BLOCKS)),
                    geo, app, con, out, tid);
    }
}

extern "C" void kernel_launch(void* const* d_in, const int* in_sizes, int n_in,
                              void* d_out, int out_size) {
    const float* geo = (const float*)d_in[0];
    const float* app = (const float*)d_in[1];
    const float* con = (const float*)d_in[2];
    const float* W1c = (const float*)d_in[3];
    const float* b1c = (const float*)d_in[4];
    const float* W2c = (const float*)d_in[5];
    const float* b2c = (const float*)d_in[6];
    const float* W1r = (const float*)d_in[7];
    const float* b1r = (const float*)d_in[8];
    const float* W2r = (const float*)d_in[9];
    const float* b2r = (const float*)d_in[10];
    const float* W1l = (const float*)d_in[11];
    const float* b1l = (const float*)d_in[12];
    const float* W2l = (const float*)d_in[13];
    const float* b2l = (const float*)d_in[14];
    float* out = (float*)d_out;

    k_reset<<<1, 1>>>();
    k_main<<<TOTAL_BLOCKS, 256>>>(geo, app, con,
                                  W1c, b1c, W1r, b1r, W1l, b1l,
                                  W2c, b2c, W2r, b2r, W2l, b2l, out);
}

// round 6
// speedup vs baseline: 1.5780x; 1.5780x over previous
#include <cuda_runtime.h>
#include <math.h>

#define BB 2
#define NN 160
#define HH 256
#define C3 768
#define FF 512
#define NP (NN*NN)            // 25600
#define MM (BB*NN)            // 320
#define LOGIT_ELEMS (BB*NP*2) // 102400 per head
#define EMB_OFF (3*LOGIT_ELEMS)

// PQ scratch, split-K2: [h = (t*2+s)*2+ks][m][f]
__device__ float g_PQ[3 * 2 * 2 * MM * FF];

#define FFMA2(acc, a, b) asm("fma.rn.f32x2 %0, %1, %2, %0;" : "+l"(acc) : "l"(a), "l"(b))
#define PACKDUP(d, x)    asm("mov.b64 %0, {%1, %1};" : "=l"(d) : "r"(__float_as_uint(x)))
#define UNPK(lo, hi, v)  asm("mov.b64 {%0, %1}, %2;" : "=r"(lo), "=r"(hi) : "l"(v))

#define BM 64
#define BN 64
#define BK 16
#define NKS 24
#define AST 68
#define GEMM_BLOCKS 480
#define WRA_BLOCKS 1400     // k1 writer: first 1400 of 3200 tiles
#define LG_BLOCKS 150
#define WRB_BLOCKS 1800     // k2 writer: remaining 1800
#define WR_SPLIT WRA_BLOCKS

// writer: 16 pairs (same i) per 256-thread block, batched LDG (MLP=6)
// tile id wb in [0,3200): b = wb/1600, i = (wb%1600)/10, j0 = (wb%10)*16
__device__ __forceinline__ void writer_role(
    int wb,
    const float* __restrict__ geo, const float* __restrict__ app, const float* __restrict__ con,
    float* __restrict__ out, int tid)
{
    const int b = wb / 1600;
    const int rem = wb % 1600;
    const int i = rem / 10;
    const int j0 = (rem % 10) * 16;
    const size_t brow = (size_t)b * NN * HH;
    float4* dst0 = (float4*)(out + EMB_OFF) + (size_t)(b*NP + i*NN + j0) * 384;

    #pragma unroll
    for (int base = 0; base < 24; base += 6) {
        float4 vals[6];
        #pragma unroll
        for (int w = 0; w < 6; w++) {
            const int lin = tid + (base + w) * 256;   // 0..6143
            const int jj = lin / 384;
            const int u  = lin - jj * 384;
            const bool jside = (u < 192);
            const int n = jside ? (j0 + jj) : i;
            const int c = (jside ? u : (u - 192)) * 4;
            const float* bp = (c < 256) ? geo : ((c < 512) ? app : con);
            vals[w] = *(const float4*)(bp + brow + (size_t)n * HH + (c & 255));
        }
        #pragma unroll
        for (int w = 0; w < 6; w++)
            __stcs(dst0 + (base + w) * 256 + tid, vals[w]);
    }
}

// ---------------- Kernel 1: split-K2 GEMM + writer half A ----------------
__global__ __launch_bounds__(256, 5) void k1_gemm_wr(
    const float* __restrict__ geo, const float* __restrict__ app, const float* __restrict__ con,
    const float* __restrict__ W1c, const float* __restrict__ b1c,
    const float* __restrict__ W1r, const float* __restrict__ b1r,
    const float* __restrict__ W1l, const float* __restrict__ b1l,
    float* __restrict__ out)
{
    __shared__ float As[2][BK*AST];
    __shared__ float Bs[2][BK*BN];
    const int g = blockIdx.x;
    const int tid = threadIdx.x;

    if (g < GEMM_BLOCKS) {
        const int nt = g % 48;
        const int r  = g / 48;
        const int mt = r >> 1;
        const int ks = r & 1;
        const int t  = nt >> 4;
        const int s  = (nt >> 3) & 1;
        const int f0 = (nt & 7) * BN;
        const float* W1 = (t==0 ? W1c : (t==1 ? W1r : W1l)) + (size_t)s * C3 * FF;
        const float* b1 = (t==0 ? b1c : (t==1 ? b1r : b1l));
        const int m0 = mt * BM;
        const int kbase = ks * 384;

        const int arow = tid >> 2, av = tid & 3;
        const int kr = tid >> 4, fo = (tid & 15) * 4;
        const int rg = tid >> 4, cg = tid & 15;

        unsigned long long acc2[4][2];
        #pragma unroll
        for (int a = 0; a < 4; a++) { acc2[a][0] = 0ull; acc2[a][1] = 0ull; }

        float4 pa, pb;
        {
            const int c0 = kbase;
            const float* segp = (c0 < 256) ? geo : ((c0 < 512) ? app : con);
            pa = *(const float4*)(segp + (size_t)(m0 + arow) * HH + (c0 & 255) + av * 4);
            pb = *(const float4*)(W1 + (size_t)(c0 + kr) * FF + f0 + fo);
        }
        As[0][(av*4+0)*AST + arow] = pa.x;
        As[0][(av*4+1)*AST + arow] = pa.y;
        As[0][(av*4+2)*AST + arow] = pa.z;
        As[0][(av*4+3)*AST + arow] = pa.w;
        *(float4*)&Bs[0][kr*BN + fo] = pb;
        __syncthreads();

        for (int kt = 0; kt < NKS; kt++) {
            const int cur = kt & 1;
            const int nxt = cur ^ 1;
            if (kt + 1 < NKS) {
                const int c0 = kbase + (kt + 1) * BK;
                const float* segp = (c0 < 256) ? geo : ((c0 < 512) ? app : con);
                pa = *(const float4*)(segp + (size_t)(m0 + arow) * HH + (c0 & 255) + av * 4);
                pb = *(const float4*)(W1 + (size_t)(c0 + kr) * FF + f0 + fo);
            }
            #pragma unroll
            for (int k = 0; k < BK; k++) {
                const float4 a4 = *(const float4*)&As[cur][k*AST + rg*4];
                const ulonglong2 b2v = *(const ulonglong2*)&Bs[cur][k*BN + cg*4];
                float avv[4] = {a4.x, a4.y, a4.z, a4.w};
                #pragma unroll
                for (int a = 0; a < 4; a++) {
                    unsigned long long ad;
                    PACKDUP(ad, avv[a]);
                    FFMA2(acc2[a][0], ad, b2v.x);
                    FFMA2(acc2[a][1], ad, b2v.y);
                }
            }
            if (kt + 1 < NKS) {
                __syncthreads();
                As[nxt][(av*4+0)*AST + arow] = pa.x;
                As[nxt][(av*4+1)*AST + arow] = pa.y;
                As[nxt][(av*4+2)*AST + arow] = pa.z;
                As[nxt][(av*4+3)*AST + arow] = pa.w;
                *(float4*)&Bs[nxt][kr*BN + fo] = pb;
                __syncthreads();
            }
        }

        const bool addb = (s == 1) && (ks == 0);
        float bv[4] = {0.f, 0.f, 0.f, 0.f};
        if (addb) {
            const float4 tb = *(const float4*)(b1 + f0 + cg*4);
            bv[0]=tb.x; bv[1]=tb.y; bv[2]=tb.z; bv[3]=tb.w;
        }
        const size_t hb = ((size_t)((t*2 + s) * 2 + ks)) * MM * FF;
        #pragma unroll
        for (int a = 0; a < 4; a++) {
            const int m = m0 + rg*4 + a;
            unsigned int lo0, hi0, lo1, hi1;
            UNPK(lo0, hi0, acc2[a][0]);
            UNPK(lo1, hi1, acc2[a][1]);
            *(float4*)(g_PQ + hb + (size_t)m * FF + f0 + cg*4) =
                make_float4(__uint_as_float(lo0) + bv[0], __uint_as_float(hi0) + bv[1],
                            __uint_as_float(lo1) + bv[2], __uint_as_float(hi1) + bv[3]);
        }
    } else {
        writer_role(g - GEMM_BLOCKS, geo, app, con, out, tid);
    }
}

// ---------------- Kernel 2: logits (32i x 32j, acc[4]) + writer half B ----------------
__global__ __launch_bounds__(256, 6) void k2_lg_wr(
    const float* __restrict__ geo, const float* __restrict__ app, const float* __restrict__ con,
    float* __restrict__ out,
    const float* __restrict__ W2c, const float* __restrict__ b2c,
    const float* __restrict__ W2r, const float* __restrict__ b2r,
    const float* __restrict__ W2l, const float* __restrict__ b2l)
{
    __shared__ float sP[32 * 132];
    __shared__ float sQ[32 * 128];
    __shared__ float sW[128];
    const int g = blockIdx.x;
    const int tid = threadIdx.x;

    if (g < LG_BLOCKS) {
        const int t = g / 50;
        const int r50 = g % 50;
        const int b = r50 / 25;
        const int r25 = r50 % 25;
        const int i0 = (r25 / 5) * 32;
        const int j0 = (r25 % 5) * 32;
        const float* W2 = (t==0 ? W2c : (t==1 ? W2r : W2l));
        const float* b2 = (t==0 ? b2c : (t==1 ? b2r : b2l));
        const size_t boff = (size_t)b * NN * FF;
        const float* P0 = g_PQ + ((size_t)((t*2+0)*2+0)) * MM * FF + boff;
        const float* P1 = g_PQ + ((size_t)((t*2+0)*2+1)) * MM * FF + boff;
        const float* Q0 = g_PQ + ((size_t)((t*2+1)*2+0)) * MM * FF + boff;
        const float* Q1 = g_PQ + ((size_t)((t*2+1)*2+1)) * MM * FF + boff;
        const int il = tid >> 5, jl = tid & 31;
        const int lr = tid >> 3, lv = tid & 7;

        float acc[4] = {0.f, 0.f, 0.f, 0.f};
        for (int fc = 0; fc < 4; fc++) {
            const int f0 = fc * 128;
            {
                const size_t ro = (size_t)(j0 + lr) * FF + f0;
                float* dp = sP + lr * 132;
                #pragma unroll
                for (int u = 0; u < 4; u++) {
                    const int fl = (lv + u * 8) * 4;
                    const float4 x = *(const float4*)(P0 + ro + fl);
                    const float4 y = *(const float4*)(P1 + ro + fl);
                    *(float4*)(dp + fl) = make_float4(x.x+y.x, x.y+y.y, x.z+y.z, x.w+y.w);
                }
            }
            {
                const size_t ro = (size_t)(i0 + lr) * FF + f0;
                float* dp = sQ + lr * 128;
                #pragma unroll
                for (int u = 0; u < 4; u++) {
                    const int fl = (lv + u * 8) * 4;
                    const float4 x = *(const float4*)(Q0 + ro + fl);
                    const float4 y = *(const float4*)(Q1 + ro + fl);
                    *(float4*)(dp + fl) = make_float4(x.x+y.x, x.y+y.y, x.z+y.z, x.w+y.w);
                }
            }
            if (tid < 128) {
                const float2 w2v = ((const float2*)W2)[f0 + tid];
                sW[tid] = w2v.x - w2v.y;
            }
            __syncthreads();

            const float* pr = sP + jl * 132;
            const float* q0 = sQ + (il * 4) * 128;
            #pragma unroll 4
            for (int f = 0; f < 128; f += 4) {
                const float4 p = *(const float4*)(pr + f);
                const float4 w = *(const float4*)(sW + f);
                #pragma unroll
                for (int a = 0; a < 4; a++) {
                    const float4 q = *(const float4*)(q0 + a * 128 + f);
                    acc[a] = fmaf(fmaxf(p.x + q.x, 0.f), w.x, acc[a]);
                    acc[a] = fmaf(fmaxf(p.y + q.y, 0.f), w.y, acc[a]);
                    acc[a] = fmaf(fmaxf(p.z + q.z, 0.f), w.z, acc[a]);
                    acc[a] = fmaf(fmaxf(p.w + q.w, 0.f), w.w, acc[a]);
                }
            }
            __syncthreads();
        }

        const float bd = b2[0] - b2[1];
        float2* o = (float2*)(out + (size_t)t * LOGIT_ELEMS) + (size_t)b * NP;
        const int j = j0 + jl;
        #pragma unroll
        for (int a = 0; a < 4; a++) {
            const float d = acc[a] + bd;
            const float p0 = 1.0f / (1.0f + __expf(-d));
            o[(size_t)(i0 + il*4 + a) * NN + j] = make_float2(p0, 1.0f - p0);
        }
    } else {
        writer_role(WR_SPLIT + (g - LG_BLOCKS), geo, app, con, out, tid);
    }
}

extern "C" void kernel_launch(void* const* d_in, const int* in_sizes, int n_in,
                              void* d_out, int out_size) {
    const float* geo = (const float*)d_in[0];
    const float* app = (const float*)d_in[1];
    const float* con = (const float*)d_in[2];
    const float* W1c = (const float*)d_in[3];
    const float* b1c = (const float*)d_in[4];
    const float* W2c = (const float*)d_in[5];
    const float* b2c = (const float*)d_in[6];
    const float* W1r = (const float*)d_in[7];
    const float* b1r = (const float*)d_in[8];
    const float* W2r = (const float*)d_in[9];
    const float* b2r = (const float*)d_in[10];
    const float* W1l = (const float*)d_in[11];
    const float* b1l = (const float*)d_in[12];
    const float* W2l = (const float*)d_in[13];
    const float* b2l = (const float*)d_in[14];
    float* out = (float*)d_out;

    k1_gemm_wr<<<GEMM_BLOCKS + WRA_BLOCKS, 256>>>(geo, app, con,
                                                  W1c, b1c, W1r, b1r, W1l, b1l, out);
    k2_lg_wr<<<LG_BLOCKS + WRB_BLOCKS, 256>>>(geo, app, con, out,
                                              W2c, b2c, W2r, b2r, W2l, b2l);
}